// round 14
// baseline (speedup 1.0000x reference)
#include <cuda_runtime.h>
#include <cuda_fp16.h>
#include <cstdint>

#define B_  8
#define D_  256
#define T_  2048
#define K_  8192
#define BT_ (B_ * T_)
#define ZQ_ELEMS (BT_ * D_)
#define NTILES 8192                  // (BT_/128) * (K_/128)

// ---------------- device scratch ----------------
__device__ __half g_zhi[BT_ * D_];   // [m][d] fp16 hi of z
__device__ __half g_zlo[BT_ * D_];   // [m][d] fp16 lo of z
__device__ __half g_chi[K_ * D_];    // [n][d] fp16 hi of 512*cb
__device__ __half g_clo[K_ * D_];    // [n][d] fp16 lo of 512*cb
__device__ float g_s1[BT_];
__device__ float g_s2[K_];
__device__ unsigned long long g_best[BT_];
__device__ double g_loss;

#define CP16(sa, ga) asm volatile("cp.async.cg.shared.global [%0], [%1], 16;" \
    :: "r"((uint32_t)(sa)), "l"(ga) : "memory")
#define CP_COMMIT()  asm volatile("cp.async.commit_group;" ::: "memory")

__device__ __forceinline__ uint32_t smem_u32(const void* p) {
    uint32_t a;
    asm("{ .reg .u64 t; cvta.to.shared.u64 t, %1; cvt.u32.u64 %0, t; }"
        : "=r"(a) : "l"(p));
    return a;
}

#define LDM4(r, addr) \
    asm volatile("ldmatrix.sync.aligned.m8n8.x4.shared.b16 {%0,%1,%2,%3}, [%4];" \
        : "=r"((r)[0]), "=r"((r)[1]), "=r"((r)[2]), "=r"((r)[3]) : "r"(addr))

// ------- split codebook (x512) -> fp16 hi/lo [K][D] + s2 (+g_loss init) -------
__global__ void split_cb_kernel(const float* __restrict__ cb) {
    if (blockIdx.x == 0 && threadIdx.x == 0) g_loss = 0.0;
    int w = threadIdx.x >> 5, lane = threadIdx.x & 31;
    int n = blockIdx.x * 8 + w;
    size_t base = (size_t)n * D_;
    double s = 0.0;
    #pragma unroll
    for (int i = 0; i < 8; i++) {
        float v = cb[base + lane + 32 * i];
        s += (double)v * v;
        float vs = v * 512.0f;                 // exact
        __half hi = __float2half_rn(vs);
        float hif = __half2float(hi);          // exact
        __half lo = __float2half_rn(vs - hif);
        g_chi[base + lane + 32 * i] = hi;
        g_clo[base + lane + 32 * i] = lo;
    }
    #pragma unroll
    for (int o = 16; o; o >>= 1) s += __shfl_xor_sync(0xffffffffu, s, o);
    if (lane == 0) g_s2[n] = (float)s;
}

// ------- split z -> fp16 hi/lo [m][d] + s1 (+g_best init) -------
__global__ void split_z_kernel(const float* __restrict__ z) {
    __shared__ float  sz[32][257];
    __shared__ double sred[8][33];
    int m0 = blockIdx.x * 32;
    int b  = m0 >> 11;
    int t0 = m0 & 2047;
    int tt = threadIdx.x & 31;
    int dp = threadIdx.x >> 5;
    if (dp == 0) g_best[m0 + tt] = 0xFFFFFFFFFFFFFFFFULL;
    double s = 0.0;
    #pragma unroll
    for (int di = 0; di < 32; di++) {
        int d = dp * 32 + di;
        float v = z[((size_t)b * D_ + d) * T_ + t0 + tt];
        sz[tt][d] = v;
        s += (double)v * v;
    }
    sred[dp][tt] = s;
    __syncthreads();
    if (dp == 0) {
        double tot = 0.0;
        #pragma unroll
        for (int p = 0; p < 8; p++) tot += sred[p][tt];
        g_s1[m0 + tt] = (float)tot;
    }
    #pragma unroll
    for (int r8 = 0; r8 < 4; r8++) {
        int row = dp * 4 + r8;
        size_t base = (size_t)(m0 + row) * D_;
        #pragma unroll
        for (int i = 0; i < 8; i++) {
            int d = tt + 32 * i;
            float v  = sz[row][d];
            __half hi = __float2half_rn(v);
            float hif = __half2float(hi);
            __half lo = __float2half_rn(v - hif);
            g_zhi[base + d] = hi;
            g_zlo[base + d] = lo;
        }
    }
}

// -------- dist: persistent CTAs, fp16 mma 3-pass, 3-stage pipeline ----------
// CTA tile 128m x 128n, BK=32, 8 chunks/tile; pipeline continuous across tiles.
// Swizzled smem: 64B rows, unit (r,q) at r*64 + ((q ^ ((r>>1)&3))<<4).
#define MATB 8192                     // 128 rows * 64 B
#define STB  (4 * MATB)               // 32768 per stage
#define NST  3
#define SMEM_BYTES (NST * STB)        // 98304
#define NCHT 8                        // k-chunks per tile

__device__ __forceinline__ void mma_fp16(float* c, const uint32_t* a,
                                         uint32_t b0, uint32_t b1) {
    asm("mma.sync.aligned.m16n8k16.row.col.f32.f16.f16.f32 "
        "{%0,%1,%2,%3}, {%4,%5,%6,%7}, {%8,%9}, {%0,%1,%2,%3};"
        : "+f"(c[0]), "+f"(c[1]), "+f"(c[2]), "+f"(c[3])
        : "r"(a[0]), "r"(a[1]), "r"(a[2]), "r"(a[3]), "r"(b0), "r"(b1));
}

// Issue one 32-k chunk (global chunk index ci) into stage stg.
__device__ __forceinline__ void issue_chunk_p(
    uint32_t sbase, int ci, int stg, int bid, int grid,
    int srow, int q0, uint32_t so0, uint32_t so1)
{
    int gt  = bid + (ci >> 3) * grid;       // global tile id
    int m0i = (gt >> 6) << 7;
    int n0i = (gt & 63) << 7;
    ptrdiff_t dd = (ptrdiff_t)((ci & 7) * 32);
    const __half* pA = g_zhi + (size_t)(m0i + srow) * D_ + q0 * 8 + dd;
    const __half* pB = g_chi + (size_t)(n0i + srow) * D_ + q0 * 8 + dd;
    const ptrdiff_t LOO = (ptrdiff_t)BT_ * D_;
    const ptrdiff_t LOC = (ptrdiff_t)K_ * D_;
    uint32_t s0 = sbase + (uint32_t)stg * STB;
    CP16(s0 + so0,            pA);
    CP16(s0 + so1,            pA + 8);
    CP16(s0 + MATB + so0,     pA + LOO);
    CP16(s0 + MATB + so1,     pA + LOO + 8);
    CP16(s0 + 2 * MATB + so0, pB);
    CP16(s0 + 2 * MATB + so1, pB + 8);
    CP16(s0 + 3 * MATB + so0, pB + LOC);
    CP16(s0 + 3 * MATB + so1, pB + LOC + 8);
    CP_COMMIT();
}

__global__ void __launch_bounds__(256, 2)
dist_mma_kernel() {
    extern __shared__ char smem[];
    uint32_t sbase = smem_u32(smem);

    int bid  = blockIdx.x;
    int grid = gridDim.x;
    int ntiles = (NTILES - bid + grid - 1) / grid;
    if (ntiles <= 0) return;
    int NTOT = ntiles * NCHT;

    int tid  = threadIdx.x;
    int wid  = tid >> 5, lane = tid & 31;
    int g    = lane >> 2;
    int tig  = lane & 3;
    int wm   = wid >> 1;       // 0..3
    int wn   = wid & 1;        // 0..1

    // ---- ldmatrix swizzled per-lane offsets ----
    int aRow = (lane & 7) + ((lane >> 3) & 1) * 8;
    int u0A  = lane >> 4;
    int swA  = (aRow >> 1) & 3;
    int bRow = (lane & 7) + (lane >> 4) * 8;
    int ub0  = (lane >> 3) & 1;
    int swB  = (bRow >> 1) & 3;
    uint32_t offA_k[2], offB_k[2];
    offA_k[0] = (uint32_t)((wm * 32 + aRow) * 64 + (((u0A + 0) ^ swA) << 4));
    offA_k[1] = (uint32_t)((wm * 32 + aRow) * 64 + (((u0A + 2) ^ swA) << 4));
    offB_k[0] = (uint32_t)((wn * 64 + bRow) * 64 + (((ub0 + 0) ^ swB) << 4));
    offB_k[1] = (uint32_t)((wn * 64 + bRow) * 64 + (((ub0 + 2) ^ swB) << 4));

    // ---- cp.async swizzled offsets ----
    int srow = tid >> 1;
    int swS  = (srow >> 1) & 3;
    int q0 = (tid & 1) * 2;
    uint32_t so0 = (uint32_t)(srow * 64 + (((q0 + 0) ^ swS) << 4));
    uint32_t so1 = (uint32_t)(srow * 64 + (((q0 + 1) ^ swS) << 4));

    float acc[2][8][4];
    #pragma unroll
    for (int mt = 0; mt < 2; mt++)
        #pragma unroll
        for (int nt = 0; nt < 8; nt++)
            #pragma unroll
            for (int q = 0; q < 4; q++) acc[mt][nt][q] = 0.0f;

    issue_chunk_p(sbase, 0, 0, bid, grid, srow, q0, so0, so1);
    if (NTOT > 1) issue_chunk_p(sbase, 1, 1, bid, grid, srow, q0, so0, so1);

    int stC = 0, stI = 2;   // compute stage, next issue stage
    for (int ci = 0; ci < NTOT; ci++) {
        if (ci < NTOT - 1) asm volatile("cp.async.wait_group 1;" ::: "memory");
        else               asm volatile("cp.async.wait_group 0;" ::: "memory");
        __syncthreads();
        // stage stI was fully consumed at iteration ci-1 (proven by barrier)
        if (ci + 2 < NTOT)
            issue_chunk_p(sbase, ci + 2, stI, bid, grid, srow, q0, so0, so1);

        uint32_t mAh = sbase + (uint32_t)stC * STB;
        uint32_t mAl = mAh + MATB;
        uint32_t mBh = mAh + 2 * MATB;
        uint32_t mBl = mAh + 3 * MATB;

        #pragma unroll
        for (int kh = 0; kh < 2; kh++) {
            uint32_t oA = offA_k[kh], oB = offB_k[kh];
            uint32_t ah[2][4], al[2][4], bb[4][4];
            #pragma unroll
            for (int p = 0; p < 4; p++)
                LDM4(bb[p], mBh + oB + (uint32_t)(p * 1024));
            LDM4(ah[0], mAh + oA);
            LDM4(ah[1], mAh + oA + 1024);

            // pass 1: hi*hi (A-lo loads interleaved)
            mma_fp16(acc[0][0], ah[0], bb[0][0], bb[0][1]);
            mma_fp16(acc[1][0], ah[1], bb[0][0], bb[0][1]);
            mma_fp16(acc[0][1], ah[0], bb[0][2], bb[0][3]);
            mma_fp16(acc[1][1], ah[1], bb[0][2], bb[0][3]);
            LDM4(al[0], mAl + oA);
            mma_fp16(acc[0][2], ah[0], bb[1][0], bb[1][1]);
            mma_fp16(acc[1][2], ah[1], bb[1][0], bb[1][1]);
            mma_fp16(acc[0][3], ah[0], bb[1][2], bb[1][3]);
            mma_fp16(acc[1][3], ah[1], bb[1][2], bb[1][3]);
            LDM4(al[1], mAl + oA + 1024);
            #pragma unroll
            for (int p = 2; p < 4; p++) {
                mma_fp16(acc[0][2 * p],     ah[0], bb[p][0], bb[p][1]);
                mma_fp16(acc[1][2 * p],     ah[1], bb[p][0], bb[p][1]);
                mma_fp16(acc[0][2 * p + 1], ah[0], bb[p][2], bb[p][3]);
                mma_fp16(acc[1][2 * p + 1], ah[1], bb[p][2], bb[p][3]);
            }
            // pass 2: lo*hi; overwrite Bh[p] with B-lo[p] after last use
            #pragma unroll
            for (int p = 0; p < 4; p++) {
                mma_fp16(acc[0][2 * p],     al[0], bb[p][0], bb[p][1]);
                mma_fp16(acc[1][2 * p],     al[1], bb[p][0], bb[p][1]);
                mma_fp16(acc[0][2 * p + 1], al[0], bb[p][2], bb[p][3]);
                mma_fp16(acc[1][2 * p + 1], al[1], bb[p][2], bb[p][3]);
                LDM4(bb[p], mBl + oB + (uint32_t)(p * 1024));
            }
            // pass 3: hi*lo
            #pragma unroll
            for (int p = 0; p < 4; p++) {
                mma_fp16(acc[0][2 * p],     ah[0], bb[p][0], bb[p][1]);
                mma_fp16(acc[1][2 * p],     ah[1], bb[p][0], bb[p][1]);
                mma_fp16(acc[0][2 * p + 1], ah[0], bb[p][2], bb[p][3]);
                mma_fp16(acc[1][2 * p + 1], ah[1], bb[p][2], bb[p][3]);
            }
        }
        stC = (stC == 2) ? 0 : stC + 1;
        stI = (stI == 2) ? 0 : stI + 1;

        // ----- per-tile epilogue (overlaps next tile's in-flight loads) -----
        if ((ci & 7) == 7) {
            int gt  = bid + (ci >> 3) * grid;
            int m0  = (gt >> 6) << 7;
            int n0  = (gt & 63) << 7;
            #pragma unroll
            for (int mt = 0; mt < 2; mt++) {
                int row0 = m0 + wm * 32 + mt * 16 + g;
                int row1 = row0 + 8;
                float s1a = __ldg(&g_s1[row0]);
                float s1b = __ldg(&g_s1[row1]);
                unsigned long long k0 = 0xFFFFFFFFFFFFFFFFULL;
                unsigned long long k1 = 0xFFFFFFFFFFFFFFFFULL;
                #pragma unroll
                for (int nt = 0; nt < 8; nt++) {
                    int nb = n0 + wn * 64 + nt * 8 + 2 * tig;
                    #pragma unroll
                    for (int q = 0; q < 2; q++) {
                        int n = nb + q;
                        float s2v = __ldg(&g_s2[n]);
                        {
                            float f = __fmaf_rn(-0.00390625f, acc[mt][nt][q], s1a) + s2v;
                            unsigned u = __float_as_uint(f);
                            u = (u & 0x80000000u) ? ~u : (u | 0x80000000u);
                            unsigned long long key =
                                ((unsigned long long)u << 32) | (unsigned)n;
                            k0 = k0 < key ? k0 : key;
                        }
                        {
                            float f = __fmaf_rn(-0.00390625f, acc[mt][nt][q + 2], s1b) + s2v;
                            unsigned u = __float_as_uint(f);
                            u = (u & 0x80000000u) ? ~u : (u | 0x80000000u);
                            unsigned long long key =
                                ((unsigned long long)u << 32) | (unsigned)n;
                            k1 = k1 < key ? k1 : key;
                        }
                        acc[mt][nt][q] = 0.0f;
                        acc[mt][nt][q + 2] = 0.0f;
                    }
                }
                #pragma unroll
                for (int o = 1; o <= 2; o <<= 1) {
                    unsigned long long t0 = __shfl_xor_sync(0xffffffffu, k0, o);
                    unsigned long long t1 = __shfl_xor_sync(0xffffffffu, k1, o);
                    k0 = k0 < t0 ? k0 : t0;
                    k1 = k1 < t1 ? k1 : t1;
                }
                if (tig == 0) {
                    atomicMin(&g_best[row0], k0);
                    atomicMin(&g_best[row1], k1);
                }
            }
        }
    }
}

// ---------------- gather z_q_st, indices, loss ----------------
__global__ void gather_kernel(const float* __restrict__ z,
                              const float* __restrict__ cb,
                              float* __restrict__ out, int out_size) {
    __shared__ float sm[32][257];
    __shared__ int   sidx[32];
    __shared__ double ssum[8];
    int m0 = blockIdx.x * 32;
    int b  = m0 >> 11;
    int t0 = m0 & 2047;
    int tid = threadIdx.x;

    if (tid < 32) {
        int idx = (int)(g_best[m0 + tid] & 0xFFFFFFFFULL);
        sidx[tid] = idx;
        if (out_size >= ZQ_ELEMS + BT_)
            out[ZQ_ELEMS + m0 + tid] = (float)idx;
    }
    __syncthreads();
    #pragma unroll
    for (int r = 0; r < 32; r++)      // unrolled: 32 independent LDGs in flight
        sm[r][tid] = cb[(size_t)sidx[r] * D_ + tid];
    __syncthreads();

    int tt = tid & 31, dp = tid >> 5;
    double lsum = 0.0;
    #pragma unroll 4
    for (int it = 0; it < 32; it++) {
        int d = dp * 32 + it;
        size_t oi = ((size_t)b * D_ + d) * T_ + t0 + tt;
        float zq = sm[tt][d];
        float zv = z[oi];
        float r  = zq - zv;
        out[oi]  = zv + r;
        lsum += (double)r * r;
    }
    #pragma unroll
    for (int o = 16; o; o >>= 1) lsum += __shfl_xor_sync(0xffffffffu, lsum, o);
    if (tt == 0) ssum[dp] = lsum;
    __syncthreads();
    if (tid == 0) {
        double tot = 0.0;
        #pragma unroll
        for (int p = 0; p < 8; p++) tot += ssum[p];
        atomicAdd(&g_loss, tot);
    }
}

__global__ void finalize_kernel(float* __restrict__ out, int out_size) {
    if (out_size >= ZQ_ELEMS + BT_ + 1)
        out[ZQ_ELEMS + BT_] = (float)(1.1 * g_loss / (double)ZQ_ELEMS);
}

// ---------------- launch ----------------
extern "C" void kernel_launch(void* const* d_in, const int* in_sizes, int n_in,
                              void* d_out, int out_size) {
    const float* z  = (const float*)d_in[0];
    const float* cb = (const float*)d_in[1];
    if (n_in >= 2 && in_sizes[0] == K_ * D_ && in_sizes[1] == ZQ_ELEMS) {
        const float* t = z; z = cb; cb = t;
    }
    float* out = (float*)d_out;

    cudaFuncSetAttribute(dist_mma_kernel,
                         cudaFuncAttributeMaxDynamicSharedMemorySize, SMEM_BYTES);

    int nsm = 148;
    cudaDeviceGetAttribute(&nsm, cudaDevAttrMultiProcessorCount, 0);
    int grid = 2 * nsm;
    if (grid > NTILES) grid = NTILES;

    split_cb_kernel<<<K_ / 8, 256>>>(cb);
    split_z_kernel<<<BT_ / 32, 256>>>(z);

    dist_mma_kernel<<<grid, 256, SMEM_BYTES>>>();   // persistent CTAs

    gather_kernel<<<BT_ / 32, 256>>>(z, cb, out, out_size);
    finalize_kernel<<<1, 1>>>(out, out_size);
}